// round 13
// baseline (speedup 1.0000x reference)
#include <cuda_runtime.h>
#include <math.h>

#define B    32
#define L    2048
#define DC   512
#define DQ   1024
#define H    256
#define NW   7
#define NIC  16          // i-chunks for query GEMMs (1024/64)
#define ICR  64          // rows per i-chunk
#define NBLK 128
#define NTHR 512

// scratch (no allocations allowed)
__device__ float g_pre[2][B][H][NIC];   // [m][b][j][ic] — contiguous ic for k2
__device__ float g_spart[B][NW][4];     // per-slice partial scores
__device__ unsigned g_cnt[B];           // per-batch arrival counters (monotonic)

// ---------------------------------------------------------------------------
// Kernel 1: query GEMM partials (batch-shared weight tiles)
// grid: 128 blocks x 512 threads
// ---------------------------------------------------------------------------
__global__ void __launch_bounds__(NTHR)
k1_gemm(const float* __restrict__ query,
        const float* __restrict__ Wq,
        const float* __restrict__ W1)
{
    int bx = blockIdx.x;        // 0..127
    int t  = threadIdx.x;       // 0..511

    __shared__ float sW[ICR * 64];     // 16 KB
    __shared__ float sq[B * ICR];      //  8 KB

    int m  = bx & 1;            // 0: Wq, 1: W1 query-half
    int jc = (bx >> 1) & 3;     // j-chunk (64 cols)
    int ic = bx >> 3;           // i-chunk (64 rows)
    const float* W = m ? (W1 + (size_t)DC * H) : Wq;
    int i0 = ic * ICR;
    int j0 = jc * 64;

    for (int idx = t; idx < ICR * 16; idx += NTHR) {
        int r  = idx >> 4;
        int c4 = idx & 15;
        *((float4*)&sW[r * 64 + c4 * 4]) =
            *((const float4*)(W + (size_t)(i0 + r) * H + j0 + c4 * 4));
    }
    {
        int b8 = t >> 4;
        int c4 = t & 15;
        *((float4*)&sq[b8 * ICR + c4 * 4]) =
            *((const float4*)(query + (size_t)b8 * DQ + i0 + c4 * 4));
    }
    __syncthreads();

    int jt = t & 15;            // 4 j's each
    int bb = t >> 4;            // batch 0..31
    float a0 = 0.f, a1 = 0.f, a2 = 0.f, a3 = 0.f;
#pragma unroll 8
    for (int i = 0; i < ICR; i++) {
        float4 w = *((const float4*)&sW[i * 64 + jt * 4]);
        float qv = sq[bb * ICR + i];
        a0 += qv * w.x; a1 += qv * w.y; a2 += qv * w.z; a3 += qv * w.w;
    }
    int jb = j0 + jt * 4;
    g_pre[m][bb][jb + 0][ic] = a0;
    g_pre[m][bb][jb + 1][ic] = a1;
    g_pre[m][bb][jb + 2][ic] = a2;
    g_pre[m][bb][jb + 3][ic] = a3;
}

// ---------------------------------------------------------------------------
// Kernel 2: params + ctx-MLP slice + last-arrival finalize
// grid: 128 blocks (32 batches x 4 H-slices) x 512 threads
// ---------------------------------------------------------------------------
__global__ void __launch_bounds__(NTHR)
k2_rest(const float* __restrict__ ctx,
        const float* __restrict__ kappa_prev,
        const float* __restrict__ bq,
        const float* __restrict__ Ws,
        const float* __restrict__ bs,
        const float* __restrict__ W1,
        const float* __restrict__ b1,
        const float* __restrict__ W2,
        const float* __restrict__ b2,
        float* __restrict__ out)
{
    int bx = blockIdx.x;        // 0..127
    int t  = threadIdx.x;       // 0..511
    int lane = t & 31;
    int wid  = t >> 5;          // 0..15

    __shared__ struct {
        float ctx[NW * DC];                 // 14 KB
        float red[16 * NW * 64];            // 28 KB
        float qt[64];
        float params[4];
    } sm;
    __shared__ float swr[3][16];
    __shared__ float swr3[NW][2];
    __shared__ float spw[NW];
    __shared__ int   s_last;

    int b     = bx >> 2;
    int slice = bx & 3;

    // zero-fill this block's p_ctx chunk = exactly (batch b, slice) segment.
    // Ordered before finalize by this block's g_cnt[b] arrival + fences.
    if (t < 128) {
        float4 z = make_float4(0.f, 0.f, 0.f, 0.f);
        ((float4*)(out + (size_t)B * DC + (size_t)bx * NTHR))[t] = z;
    }

    // h-pre reduce: 4 independent float4 loads per j (contiguous ic)
    float hval = 0.f;
    if (t < H) {
        const float4* p = (const float4*)&g_pre[0][b][t][0];
        float4 x0 = p[0], x1 = p[1], x2 = p[2], x3 = p[3];
        float s = bq[t]
            + ((x0.x + x0.y) + (x0.z + x0.w))
            + ((x1.x + x1.y) + (x1.z + x1.w))
            + ((x2.x + x2.y) + (x2.z + x2.w))
            + ((x3.x + x3.y) + (x3.z + x3.w));
        hval = tanhf(s);
    }
    // qtot for this slice (t<64)
    if (t < 64) {
        int j = slice * 64 + t;
        const float4* p = (const float4*)&g_pre[1][b][j][0];
        float4 x0 = p[0], x1 = p[1], x2 = p[2], x3 = p[3];
        sm.qt[t] = b1[j]
            + ((x0.x + x0.y) + (x0.z + x0.w))
            + ((x1.x + x1.y) + (x1.z + x1.w))
            + ((x2.x + x2.y) + (x2.z + x2.w))
            + ((x3.x + x3.y) + (x3.z + x3.w));
    }

    // stat = h @ Ws + bs
    float v0 = 0.f, v1 = 0.f, v2 = 0.f;
    if (t < H) {
        v0 = hval * Ws[t * 3 + 0];
        v1 = hval * Ws[t * 3 + 1];
        v2 = hval * Ws[t * 3 + 2];
    }
#pragma unroll
    for (int o = 16; o; o >>= 1) {
        v0 += __shfl_down_sync(0xffffffffu, v0, o);
        v1 += __shfl_down_sync(0xffffffffu, v1, o);
        v2 += __shfl_down_sync(0xffffffffu, v2, o);
    }
    if (lane == 0) { swr[0][wid] = v0; swr[1][wid] = v1; swr[2][wid] = v2; }
    __syncthreads();
    if (t == 0) {
        float s0 = bs[0], s1 = bs[1], s2 = bs[2];
#pragma unroll
        for (int w = 0; w < 16; w++) { s0 += swr[0][w]; s1 += swr[1][w]; s2 += swr[2][w]; }
        float kappa = expf(s2) + kappa_prev[b];
        sm.params[0] = expf(s0);
        sm.params[1] = expf(s1);
        sm.params[2] = kappa;
        sm.params[3] = rintf(kappa);        // jnp.round = round-half-even
    }
    __syncthreads();
    int center = (int)sm.params[3];

    // stage 7 ctx rows (zero-filled out of range)
    for (int c = t; c < NW * (DC / 4); c += NTHR) {
        int w  = c / (DC / 4);
        int i4 = c % (DC / 4);
        int l  = center - 3 + w;
        float4 v = make_float4(0.f, 0.f, 0.f, 0.f);
        if (l >= 0 && l < L)
            v = ((const float4*)(ctx + ((size_t)b * L + l) * DC))[i4];
        *((float4*)&sm.ctx[w * DC + i4 * 4]) = v;
    }
    __syncthreads();

    // ctx-MLP: 32 i-groups x 16 j-threads (4 j each); all 16 W1 loads batched
    {
        int igp = t >> 4;           // 0..31, 16 i-rows each
        int jt  = t & 15;
        int j0  = slice * 64 + jt * 4;
        int i0  = igp * 16;

        float4 wv[16];
#pragma unroll
        for (int ii = 0; ii < 16; ii++)
            wv[ii] = *((const float4*)(W1 + (size_t)(i0 + ii) * H + j0));

        float ac[NW][4];
#pragma unroll
        for (int w = 0; w < NW; w++)
#pragma unroll
            for (int k = 0; k < 4; k++) ac[w][k] = 0.f;

#pragma unroll
        for (int ii = 0; ii < 16; ii++) {
#pragma unroll
            for (int w = 0; w < NW; w++) {
                float c = sm.ctx[w * DC + i0 + ii];
                ac[w][0] += c * wv[ii].x;
                ac[w][1] += c * wv[ii].y;
                ac[w][2] += c * wv[ii].z;
                ac[w][3] += c * wv[ii].w;
            }
        }

        // fold igp pairs within warp (lanes 0-15 keep), dump once
#pragma unroll
        for (int w = 0; w < NW; w++)
#pragma unroll
            for (int k = 0; k < 4; k++) {
                float v = ac[w][k];
                v += __shfl_xor_sync(0xffffffffu, v, 16);
                if (lane < 16)
                    sm.red[(wid * NW + w) * 64 + jt * 4 + k] = v;
            }
    }
    __syncthreads();

    // single pass: 448 threads finish all 7 windows
    {
        float contrib = 0.f;
        if (t < NW * 64) {
            int w = t >> 6;
            int j = t & 63;
            float hsum = sm.qt[j];
#pragma unroll
            for (int p = 0; p < 16; p++)
                hsum += sm.red[(p * NW + w) * 64 + j];
            contrib = tanhf(hsum) * W2[slice * 64 + j];
        }
#pragma unroll
        for (int o = 16; o; o >>= 1)
            contrib += __shfl_down_sync(0xffffffffu, contrib, o);
        if (lane == 0 && wid < NW * 2) swr3[wid >> 1][wid & 1] = contrib;
        __syncthreads();
        if (t < NW)
            g_spart[b][t][slice] = swr3[t][0] + swr3[t][1];
    }
    __syncthreads();

    // arrival counter: last slice block of this batch finalizes
    if (t == 0) {
        __threadfence();
        unsigned old = atomicAdd(&g_cnt[b], 1u);
        s_last = ((old & 3u) == 3u);
    }
    __syncthreads();
    if (!s_last) return;

    // ================= finalize (winner block; sctx already in smem) =======
    if (t == 0) {
        __threadfence();    // acquire: other slices' g_spart + zero-fill stores
        float alpha = sm.params[0], beta = sm.params[1], kappa = sm.params[2];
        float b2v = b2[0];
        float pw[NW], psum = 0.f;
#pragma unroll
        for (int w = 0; w < NW; w++) {
            int l = center - 3 + w;
            float p = 0.f;
            if (l >= 0 && l < L) {
                float sc = b2v;
#pragma unroll
                for (int s2 = 0; s2 < 4; s2++) sc += *(volatile float*)&g_spart[b][w][s2];
                float d = (float)l - kappa;
                p = alpha * expf(sc - beta * d * d);
            }
            pw[w] = p;
            psum += p;
        }
        float inv = 1.f / psum;
#pragma unroll
        for (int w = 0; w < NW; w++) spw[w] = pw[w] * inv;
    }
    __syncthreads();

    // expected_ctx from smem-staged ctx rows (512 threads = DC)
    {
        float acc = 0.f;
#pragma unroll
        for (int w = 0; w < NW; w++)
            acc += spw[w] * sm.ctx[w * DC + t];
        out[(size_t)b * DC + t] = acc;
    }
    // sparse p_ctx writes (row zero-filled by batch b's own 4 slice blocks,
    // ordered before this point by their g_cnt[b] arrivals + fences)
    if (t < NW) {
        int l = center - 3 + t;
        if (l >= 0 && l < L)
            out[(size_t)B * DC + (size_t)b * L + l] = spw[t];
    }
}

// ---------------------------------------------------------------------------
extern "C" void kernel_launch(void* const* d_in, const int* in_sizes, int n_in,
                              void* d_out, int out_size)
{
    const float* query = (const float*)d_in[0];
    const float* ctx   = (const float*)d_in[1];
    const float* kprev = (const float*)d_in[2];
    const float* Wq    = (const float*)d_in[3];
    const float* bq    = (const float*)d_in[4];
    const float* Ws    = (const float*)d_in[5];
    const float* bs    = (const float*)d_in[6];
    const float* W1    = (const float*)d_in[7];
    const float* b1    = (const float*)d_in[8];
    const float* W2    = (const float*)d_in[9];
    const float* b2    = (const float*)d_in[10];

    k1_gemm<<<NBLK, NTHR>>>(query, Wq, W1);
    k2_rest<<<NBLK, NTHR>>>(ctx, kprev, bq, Ws, bs, W1, b1, W2, b2,
                            (float*)d_out);
}

// round 14
// speedup vs baseline: 1.2729x; 1.2729x over previous
#include <cuda_runtime.h>
#include <math.h>

#define B    32
#define L    2048
#define DC   512
#define DQ   1024
#define H    256
#define NW   7
#define NIC  16          // i-chunks for query GEMMs (1024/64)
#define ICR  64          // rows per i-chunk
#define NBLK 128
#define NTHR 512

// scratch (no allocations allowed)
__device__ float g_pre[2][NIC][B][H];   // [0]=h-pre partials, [1]=q-part of MLP partials
__device__ float g_spart[B][NW][4];     // per-slice partial scores
__device__ unsigned g_cnt[B];           // per-batch arrival counters (monotonic)

// ---------------------------------------------------------------------------
// Kernel 1: query GEMM partials (batch-shared weight tiles)
// grid: 128 blocks x 512 threads
// ---------------------------------------------------------------------------
__global__ void __launch_bounds__(NTHR)
k1_gemm(const float* __restrict__ query,
        const float* __restrict__ Wq,
        const float* __restrict__ W1)
{
    int bx = blockIdx.x;        // 0..127
    int t  = threadIdx.x;       // 0..511

    __shared__ float sW[ICR * 64];     // 16 KB
    __shared__ float sq[B * ICR];      //  8 KB

    int m  = bx & 1;            // 0: Wq, 1: W1 query-half
    int jc = (bx >> 1) & 3;     // j-chunk (64 cols)
    int ic = bx >> 3;           // i-chunk (64 rows)
    const float* W = m ? (W1 + (size_t)DC * H) : Wq;
    int i0 = ic * ICR;
    int j0 = jc * 64;

    for (int idx = t; idx < ICR * 16; idx += NTHR) {
        int r  = idx >> 4;
        int c4 = idx & 15;
        *((float4*)&sW[r * 64 + c4 * 4]) =
            *((const float4*)(W + (size_t)(i0 + r) * H + j0 + c4 * 4));
    }
    {
        int b8 = t >> 4;
        int c4 = t & 15;
        *((float4*)&sq[b8 * ICR + c4 * 4]) =
            *((const float4*)(query + (size_t)b8 * DQ + i0 + c4 * 4));
    }
    __syncthreads();

    int jt = t & 15;            // 4 j's each
    int bb = t >> 4;            // batch 0..31
    float a0 = 0.f, a1 = 0.f, a2 = 0.f, a3 = 0.f;
#pragma unroll 8
    for (int i = 0; i < ICR; i++) {
        float4 w = *((const float4*)&sW[i * 64 + jt * 4]);
        float qv = sq[bb * ICR + i];
        a0 += qv * w.x; a1 += qv * w.y; a2 += qv * w.z; a3 += qv * w.w;
    }
    *((float4*)&g_pre[m][ic][bb][j0 + jt * 4]) = make_float4(a0, a1, a2, a3);
}

// ---------------------------------------------------------------------------
// Kernel 2: params + ctx-MLP slice + last-arrival finalize
// grid: 128 blocks (32 batches x 4 H-slices) x 512 threads
// ---------------------------------------------------------------------------
__global__ void __launch_bounds__(NTHR)
k2_rest(const float* __restrict__ ctx,
        const float* __restrict__ kappa_prev,
        const float* __restrict__ bq,
        const float* __restrict__ Ws,
        const float* __restrict__ bs,
        const float* __restrict__ W1,
        const float* __restrict__ b1,
        const float* __restrict__ W2,
        const float* __restrict__ b2,
        float* __restrict__ out)
{
    int bx = blockIdx.x;        // 0..127
    int t  = threadIdx.x;       // 0..511
    int lane = t & 31;
    int wid  = t >> 5;          // 0..15

    __shared__ struct {
        float ctx[NW * DC];                 // 14 KB
        float red[16 * NW * 64];            // 28 KB
        float qt[64];
        float params[4];
    } sm;
    __shared__ float shpart[2][H];
    __shared__ float swr[3][16];
    __shared__ float swr3[NW][2];
    __shared__ float spw[NW];
    __shared__ int   s_last;

    int b     = bx >> 2;
    int slice = bx & 3;

    // zero-fill this block's p_ctx chunk = exactly (batch b, slice) segment.
    // Ordered before finalize by this block's g_cnt[b] arrival + fences.
    if (t < 128) {
        float4 z = make_float4(0.f, 0.f, 0.f, 0.f);
        ((float4*)(out + (size_t)B * DC + (size_t)bx * NTHR))[t] = z;
    }

    // h-pre reduce split 2-way (2 threads per j, 8 chunks each)
    {
        int j    = t & 255;
        int half = t >> 8;          // 0 or 1
        float part = 0.f;
#pragma unroll
        for (int ic = 0; ic < 8; ic++)
            part += g_pre[0][half * 8 + ic][b][j];
        shpart[half][j] = part;
    }
    // qtot for this slice (t<64)
    if (t < 64) {
        int j = slice * 64 + t;
        float qt = b1[j];
#pragma unroll
        for (int ic = 0; ic < NIC; ic++) qt += g_pre[1][ic][b][j];
        sm.qt[t] = qt;
    }
    __syncthreads();

    float hval = 0.f;
    if (t < H)
        hval = tanhf(shpart[0][t] + shpart[1][t] + bq[t]);

    // stat = h @ Ws + bs
    float v0 = 0.f, v1 = 0.f, v2 = 0.f;
    if (t < H) {
        v0 = hval * Ws[t * 3 + 0];
        v1 = hval * Ws[t * 3 + 1];
        v2 = hval * Ws[t * 3 + 2];
    }
#pragma unroll
    for (int o = 16; o; o >>= 1) {
        v0 += __shfl_down_sync(0xffffffffu, v0, o);
        v1 += __shfl_down_sync(0xffffffffu, v1, o);
        v2 += __shfl_down_sync(0xffffffffu, v2, o);
    }
    if (lane == 0) { swr[0][wid] = v0; swr[1][wid] = v1; swr[2][wid] = v2; }
    __syncthreads();
    if (t == 0) {
        float s0 = bs[0], s1 = bs[1], s2 = bs[2];
#pragma unroll
        for (int w = 0; w < 16; w++) { s0 += swr[0][w]; s1 += swr[1][w]; s2 += swr[2][w]; }
        float kappa = expf(s2) + kappa_prev[b];
        sm.params[0] = expf(s0);
        sm.params[1] = expf(s1);
        sm.params[2] = kappa;
        sm.params[3] = rintf(kappa);        // jnp.round = round-half-even
    }
    __syncthreads();
    int center = (int)sm.params[3];

    // stage 7 ctx rows (zero-filled out of range)
    for (int c = t; c < NW * (DC / 4); c += NTHR) {
        int w  = c / (DC / 4);
        int i4 = c % (DC / 4);
        int l  = center - 3 + w;
        float4 v = make_float4(0.f, 0.f, 0.f, 0.f);
        if (l >= 0 && l < L)
            v = ((const float4*)(ctx + ((size_t)b * L + l) * DC))[i4];
        *((float4*)&sm.ctx[w * DC + i4 * 4]) = v;
    }
    __syncthreads();

    // ctx-MLP: 32 i-groups x 16 j-threads (4 j each); all 16 W1 loads batched
    {
        int igp = t >> 4;           // 0..31, 16 i-rows each
        int jt  = t & 15;
        int j0  = slice * 64 + jt * 4;
        int i0  = igp * 16;

        float4 wv[16];
#pragma unroll
        for (int ii = 0; ii < 16; ii++)
            wv[ii] = *((const float4*)(W1 + (size_t)(i0 + ii) * H + j0));

        float ac[NW][4];
#pragma unroll
        for (int w = 0; w < NW; w++)
#pragma unroll
            for (int k = 0; k < 4; k++) ac[w][k] = 0.f;

#pragma unroll
        for (int ii = 0; ii < 16; ii++) {
#pragma unroll
            for (int w = 0; w < NW; w++) {
                float c = sm.ctx[w * DC + i0 + ii];
                ac[w][0] += c * wv[ii].x;
                ac[w][1] += c * wv[ii].y;
                ac[w][2] += c * wv[ii].z;
                ac[w][3] += c * wv[ii].w;
            }
        }

        // fold igp pairs within warp (lanes 0-15 keep), dump once
#pragma unroll
        for (int w = 0; w < NW; w++)
#pragma unroll
            for (int k = 0; k < 4; k++) {
                float v = ac[w][k];
                v += __shfl_xor_sync(0xffffffffu, v, 16);
                if (lane < 16)
                    sm.red[(wid * NW + w) * 64 + jt * 4 + k] = v;
            }
    }
    __syncthreads();

    // single pass: 448 threads finish all 7 windows
    {
        float contrib = 0.f;
        if (t < NW * 64) {
            int w = t >> 6;
            int j = t & 63;
            float hsum = sm.qt[j];
#pragma unroll
            for (int p = 0; p < 16; p++)
                hsum += sm.red[(p * NW + w) * 64 + j];
            contrib = tanhf(hsum) * W2[slice * 64 + j];
        }
#pragma unroll
        for (int o = 16; o; o >>= 1)
            contrib += __shfl_down_sync(0xffffffffu, contrib, o);
        if (lane == 0 && wid < NW * 2) swr3[wid >> 1][wid & 1] = contrib;
        __syncthreads();
        if (t < NW)
            g_spart[b][t][slice] = swr3[t][0] + swr3[t][1];
    }
    __syncthreads();

    // arrival counter: last slice block of this batch finalizes
    if (t == 0) {
        __threadfence();
        unsigned old = atomicAdd(&g_cnt[b], 1u);
        s_last = ((old & 3u) == 3u);
    }
    __syncthreads();
    if (!s_last) return;

    // ================= finalize (winner block; sctx already in smem) =======
    if (t == 0) {
        __threadfence();    // acquire: other slices' g_spart + zero-fill stores
        float alpha = sm.params[0], beta = sm.params[1], kappa = sm.params[2];
        float b2v = b2[0];
        float pw[NW], psum = 0.f;
#pragma unroll
        for (int w = 0; w < NW; w++) {
            int l = center - 3 + w;
            float p = 0.f;
            if (l >= 0 && l < L) {
                float sc = b2v;
#pragma unroll
                for (int s2 = 0; s2 < 4; s2++) sc += *(volatile float*)&g_spart[b][w][s2];
                float d = (float)l - kappa;
                p = alpha * expf(sc - beta * d * d);
            }
            pw[w] = p;
            psum += p;
        }
        float inv = 1.f / psum;
#pragma unroll
        for (int w = 0; w < NW; w++) spw[w] = pw[w] * inv;
    }
    __syncthreads();

    // expected_ctx from smem-staged ctx rows (512 threads = DC)
    {
        float acc = 0.f;
#pragma unroll
        for (int w = 0; w < NW; w++)
            acc += spw[w] * sm.ctx[w * DC + t];
        out[(size_t)b * DC + t] = acc;
    }
    // sparse p_ctx writes (row zero-filled by batch b's own 4 slice blocks,
    // ordered before this point by their g_cnt[b] arrivals + fences)
    if (t < NW) {
        int l = center - 3 + t;
        if (l >= 0 && l < L)
            out[(size_t)B * DC + (size_t)b * L + l] = spw[t];
    }
}

// ---------------------------------------------------------------------------
extern "C" void kernel_launch(void* const* d_in, const int* in_sizes, int n_in,
                              void* d_out, int out_size)
{
    const float* query = (const float*)d_in[0];
    const float* ctx   = (const float*)d_in[1];
    const float* kprev = (const float*)d_in[2];
    const float* Wq    = (const float*)d_in[3];
    const float* bq    = (const float*)d_in[4];
    const float* Ws    = (const float*)d_in[5];
    const float* bs    = (const float*)d_in[6];
    const float* W1    = (const float*)d_in[7];
    const float* b1    = (const float*)d_in[8];
    const float* W2    = (const float*)d_in[9];
    const float* b2    = (const float*)d_in[10];

    k1_gemm<<<NBLK, NTHR>>>(query, Wq, W1);
    k2_rest<<<NBLK, NTHR>>>(ctx, kprev, bq, Ws, bs, W1, b1, W2, b2,
                            (float*)d_out);
}